// round 14
// baseline (speedup 1.0000x reference)
#include <cuda_runtime.h>
#include <cstdint>
#include <math.h>

// ---------------- problem constants ----------------
#define NL   2
#define DDIM 1024
#define HH   16
#define HDIM 64
#define FFD  4096
#define SS   1024
#define NB   2
#define LLQ  4096
#define ROWS_T (LLQ*NB)   // 8192 query rows
#define ROWS_S (SS*NB)    // 2048 kv rows
#define SCALING 0.125f    // HD^-0.5

// ---------------- device scratch (static, allocation-free) ----------------
__device__ float g_q   [ROWS_T*DDIM];
__device__ float g_kv  [2*ROWS_S*DDIM];     // k then v
__device__ float g_attn[ROWS_T*DDIM];
__device__ float g_x1  [ROWS_T*DDIM];
__device__ float g_x   [ROWS_T*DDIM];
__device__ float g_h   [ROWS_T*FFD];
__device__ float g_y   [ROWS_T*DDIM];
__device__ float g_tgt [ROWS_T*DDIM];
__device__ float g_noise[NL*NB*HH*HDIM];
__device__ float g_m   [NB*HH*LLQ];
__device__ float g_zi  [NB*HH*LLQ];
// pre-rounded (tf32) copies
__device__ float g_ipw [NL*3*DDIM*DDIM];
__device__ float g_oww [NL*DDIM*DDIM];
__device__ float g_f1w [NL*FFD*DDIM];
__device__ float g_f2w [NL*DDIM*FFD];
__device__ float g_kvr [2*ROWS_S*DDIM];     // rounded key_in then value_in
__device__ float g_qryr[ROWS_T*DDIM];
__device__ float g_xr  [ROWS_T*DDIM];
__device__ float g_tgtr[ROWS_T*DDIM];

// ---------------- TF32 rounding ----------------
__device__ __forceinline__ float tf32r(float x) {
    asm("cvt.rna.tf32.f32 %0, %0;" : "+f"(x));
    return x;
}

// ---------------- merged pre-rounding (one launch) ----------------
struct RC {
    const float4* s[7];
    float4*       d[7];
    int           n4[7];
};
__global__ void round_all(RC rc) {
    int i = blockIdx.x * blockDim.x + threadIdx.x;
#pragma unroll
    for (int seg = 0; seg < 7; seg++) {
        if (i < rc.n4[seg]) {
            float4 t = rc.s[seg][i];
            t.x = tf32r(t.x); t.y = tf32r(t.y);
            t.z = tf32r(t.z); t.w = tf32r(t.w);
            rc.d[seg][i] = t;
            return;
        }
        i -= rc.n4[seg];
    }
}

// ---------------- cp.async helpers ----------------
__device__ __forceinline__ void cp16(void* s, const void* g) {
    uint32_t sa = (uint32_t)__cvta_generic_to_shared(s);
    asm volatile("cp.async.cg.shared.global [%0], [%1], 16;" :: "r"(sa), "l"(g));
}
__device__ __forceinline__ void cp_commit() {
    asm volatile("cp.async.commit_group;");
}
template<int N>
__device__ __forceinline__ void cp_wait() {
    asm volatile("cp.async.wait_group %0;" :: "n"(N));
}

// ---------------- ldmatrix (tf32 fragments via b16 tiles) ----------------
__device__ __forceinline__ void ldsm4(uint32_t& r0, uint32_t& r1,
                                      uint32_t& r2, uint32_t& r3, uint32_t addr) {
    asm volatile("ldmatrix.sync.aligned.m8n8.x4.shared.b16 {%0,%1,%2,%3}, [%4];"
                 : "=r"(r0), "=r"(r1), "=r"(r2), "=r"(r3) : "r"(addr));
}

// ---------------- JAX threefry2x32 (partitionable) ----------------
__device__ __forceinline__ uint32_t rotl32(uint32_t x, int d) {
    return (x << d) | (x >> (32 - d));
}
__device__ __forceinline__ void threefry2x32(uint32_t k0, uint32_t k1,
                                             uint32_t& x0, uint32_t& x1) {
    uint32_t ks2 = k0 ^ k1 ^ 0x1BD11BDAu;
    x0 += k0; x1 += k1;
#define TFR(r) { x0 += x1; x1 = rotl32(x1, (r)); x1 ^= x0; }
    TFR(13) TFR(15) TFR(26) TFR(6)
    x0 += k1; x1 += ks2 + 1u;
    TFR(17) TFR(29) TFR(16) TFR(24)
    x0 += ks2; x1 += k0 + 2u;
    TFR(13) TFR(15) TFR(26) TFR(6)
    x0 += k0; x1 += k1 + 3u;
    TFR(17) TFR(29) TFR(16) TFR(24)
    x0 += k1; x1 += ks2 + 4u;
    TFR(13) TFR(15) TFR(26) TFR(6)
    x0 += ks2; x1 += k0 + 5u;
#undef TFR
}
__device__ __forceinline__ float bits_to_normal(uint32_t b) {
    float f = __uint_as_float((b >> 9) | 0x3F800000u) - 1.0f;   // [0,1)
    const float lo = -0.99999994f;
    float u = fmaxf(lo, f * 2.0f + lo);
    return 1.4142135623730951f * erfinvf(u);
}
__global__ void noise_kernel(float* __restrict__ noise) {
    int j = blockIdx.x * blockDim.x + threadIdx.x;
    if (j >= NL * 2048) return;
    int layer = j / 2048, jj = j % 2048;
    uint32_t k0 = 0u, k1 = 42u, x0 = 0u, x1 = (uint32_t)layer;
    threefry2x32(k0, k1, x0, x1);
    uint32_t b0 = 0u, b1 = (uint32_t)jj;
    threefry2x32(x0, x1, b0, b1);
    noise[layer * 2048 + jj] = bits_to_normal(b0 ^ b1);
}

// ---------------- TF32 tensor-core GEMM (mma.sync.m16n8k8) ----------------
__device__ __forceinline__ void mma_tf32(float* d, const uint32_t* a, const uint32_t* b) {
    asm volatile(
        "mma.sync.aligned.m16n8k8.row.col.f32.tf32.tf32.f32 "
        "{%0,%1,%2,%3}, {%4,%5,%6,%7}, {%8,%9}, {%0,%1,%2,%3};\n"
        : "+f"(d[0]), "+f"(d[1]), "+f"(d[2]), "+f"(d[3])
        : "r"(a[0]), "r"(a[1]), "r"(a[2]), "r"(a[3]), "r"(b[0]), "r"(b[1]));
}

// ================= generic GEMM: 3-stage cp.async, one sync per k-step ======
template<int BM, int BN, int WM, int WN>
__global__ __launch_bounds__(256, 2)
void mma_gemm(int M, int Nn, int K,
              const float* __restrict__ A, int lda, long long sA,
              const float* __restrict__ B, int ldb, long long sB,
              const float* __restrict__ bias, int bstride, float alpha,
              const float* __restrict__ resid, int ldr, int relu, int roundc,
              float* __restrict__ C, int ldc, long long sC)
{
    constexpr int BK = 32;
    constexpr int STG = 3;
    constexpr int SA  = BK + 4;                   // 36
    constexpr int ASTG = BM * SA;
    constexpr int BSTG = BN * SA;

    extern __shared__ __align__(16) float smem[];
    float* As = smem;
    float* Bs = smem + STG * ASTG;

    long long bz = blockIdx.z;
    A += bz * sA; B += bz * sB; C += bz * sC;
    if (bias) bias += bz * bstride;
    const int bm = blockIdx.y * BM;
    const int bn = blockIdx.x * BN;
    const int tid = threadIdx.x;
    const int wid = tid >> 5, lane = tid & 31;
    const int g = lane >> 2, tq = lane & 3;
    constexpr int WX = BN / WN;
    const int wm = (wid / WX) * WM, wn = (wid % WX) * WN;
    constexpr int MA = WM / 16, NA = WN / 8;

    float acc[MA][NA][4];
#pragma unroll
    for (int i = 0; i < MA; i++)
#pragma unroll
        for (int j = 0; j < NA; j++)
#pragma unroll
            for (int e = 0; e < 4; e++) acc[i][j][e] = 0.f;

    const int ltile = lane >> 3, lr = lane & 7;
    const uint32_t s_base = (uint32_t)__cvta_generic_to_shared(smem);
    uint32_t baseA[MA];
#pragma unroll
    for (int ma = 0; ma < MA; ma++)
        baseA[ma] = ((wm + ma * 16 + (ltile & 1) * 8 + lr) * SA
                     + (ltile >> 1) * 4) * 4;
    uint32_t baseB[(NA + 1) / 2];
#pragma unroll
    for (int p = 0; p < NA / 2; p++)
        baseB[p] = ((wn + p * 16 + (ltile >> 1) * 8 + lr) * SA
                    + (ltile & 1) * 4) * 4;

    auto load_tiles = [&](int st, int k0) {
        float* as = As + st * ASTG;
        float* bs = Bs + st * BSTG;
#pragma unroll
        for (int it = 0; it < BM * BK / (4 * 256); it++) {
            int vi = tid + it * 256;
            int r  = vi >> 3;
            int kc = (vi & 7) * 4;
            cp16(&as[r * SA + kc], A + (long long)(bm + r) * lda + k0 + kc);
        }
#pragma unroll
        for (int it = 0; it < BN * BK / (4 * 256); it++) {
            int vi = tid + it * 256;
            int r  = vi >> 3;
            int kc = (vi & 7) * 4;
            cp16(&bs[r * SA + kc], B + (long long)(bn + r) * ldb + k0 + kc);
        }
    };

    const int nk = K / BK;
    load_tiles(0, 0);      cp_commit();
    load_tiles(1, BK);     cp_commit();

    for (int i = 0; i < nk; i++) {
        if (i == nk - 1) { cp_wait<0>(); } else { cp_wait<1>(); }
        __syncthreads();   // stage i published; stage (i-1) consumers all done
        if (i + 2 < nk) {  // refill buffer (i-1)%3 with stage i+2
            load_tiles((i + 2) % STG, (i + 2) * BK);
            cp_commit();
        }

        const int buf = i % STG;
        const uint32_t s_as = s_base + buf * ASTG * 4;
        const uint32_t s_bs = s_base + (STG * ASTG + buf * BSTG) * 4;

#pragma unroll
        for (int ka = 0; ka < BK / 8; ka++) {
            const int kb = ka * 8;
            uint32_t af[MA][4];
            uint32_t bf[NA][2];
#pragma unroll
            for (int ma = 0; ma < MA; ma++)
                ldsm4(af[ma][0], af[ma][1], af[ma][2], af[ma][3],
                      s_as + baseA[ma] + kb * 4);
#pragma unroll
            for (int p = 0; p < NA / 2; p++)
                ldsm4(bf[2 * p][0], bf[2 * p][1], bf[2 * p + 1][0],
                      bf[2 * p + 1][1], s_bs + baseB[p] + kb * 4);
#pragma unroll
            for (int ma = 0; ma < MA; ma++)
#pragma unroll
                for (int na = 0; na < NA; na++)
                    mma_tf32(acc[ma][na], af[ma], bf[na]);
        }
    }

#pragma unroll
    for (int ma = 0; ma < MA; ma++) {
#pragma unroll
        for (int na = 0; na < NA; na++) {
            int c0 = bn + wn + na * 8 + tq * 2;
#pragma unroll
            for (int hh = 0; hh < 2; hh++) {
                long long rr = bm + wm + ma * 16 + g + hh * 8;
                float v0 = acc[ma][na][hh * 2 + 0];
                float v1 = acc[ma][na][hh * 2 + 1];
                if (bias) { v0 += bias[c0]; v1 += bias[c0 + 1]; }
                v0 *= alpha; v1 *= alpha;
                if (resid) {
                    float2 rv = *reinterpret_cast<const float2*>(
                        resid + rr * (long long)ldr + c0);
                    v0 += rv.x; v1 += rv.y;
                }
                if (relu) { v0 = fmaxf(v0, 0.f); v1 = fmaxf(v1, 0.f); }
                if (roundc) { v0 = tf32r(v0); v1 = tf32r(v1); }
                *reinterpret_cast<float2*>(C + rr * (long long)ldc + c0) =
                    make_float2(v0, v1);
            }
        }
    }
}

// ================= fused flash attention (fast exp) =================
#define FKSTR 68
#define FPSTR 132
#define FKSTG (128*FKSTR)
#define FVOFF (2*FKSTG)
#define FPOFF (4*FKSTG)
#define FL_SMEM ((4*FKSTG + 128*FPSTR) * 4)   // 206848 B

__global__ void __launch_bounds__(256, 1)
flash_kernel(const float* __restrict__ q, const float* __restrict__ k,
             const float* __restrict__ v, const float* __restrict__ noise,
             float* __restrict__ attn, float* __restrict__ msav,
             float* __restrict__ zisav)
{
    extern __shared__ __align__(16) float sm[];
    const int z = blockIdx.y, lt = blockIdx.x;
    const int tid = threadIdx.x, wid = tid >> 5, lane = tid & 31;
    const int g = lane >> 2, tq = lane & 3;
    const int ltile = lane >> 3, lr = lane & 7;
    const int wr0 = wid * 16;
    const float* qz = q + z * 64;
    const float* kz = k + z * 64;
    const float* vz = v + z * 64;
    const uint32_t sbase = (uint32_t)__cvta_generic_to_shared(sm);

#pragma unroll
    for (int i = 0; i < 8; i++) {
        int vi = tid + i * 256; int r = vi >> 4; int c = (vi & 15) << 2;
        cp16(&sm[FPOFF + r * FKSTR + c], qz + (size_t)(lt * 128 + r) * 2048 + c);
    }
    cp_commit();
#pragma unroll
    for (int i = 0; i < 8; i++) {
        int vi = tid + i * 256; int r = vi >> 4; int c = (vi & 15) << 2;
        cp16(&sm[r * FKSTR + c], kz + (size_t)r * 2048 + c);
    }
    cp_commit();
#pragma unroll
    for (int i = 0; i < 8; i++) {
        int vi = tid + i * 256; int r = vi >> 4; int c = (vi & 15) << 2;
        cp16(&sm[FVOFF + r * FKSTR + c], vz + (size_t)r * 2048 + c);
    }
    cp_commit();

    cp_wait<2>(); __syncthreads();
    uint32_t qf[8][4];
    {
        uint32_t qaddr = sbase +
            (FPOFF + (wr0 + (ltile & 1) * 8 + lr) * FKSTR + (ltile >> 1) * 4) * 4;
#pragma unroll
        for (int ka = 0; ka < 8; ka++)
            ldsm4(qf[ka][0], qf[ka][1], qf[ka][2], qf[ka][3], qaddr + ka * 32);
    }
    __syncthreads();

    uint32_t kaddr[8];
#pragma unroll
    for (int p = 0; p < 8; p++)
        kaddr[p] = sbase + ((p * 16 + (ltile >> 1) * 8 + lr) * FKSTR
                            + (ltile & 1) * 4) * 4;
    const uint32_t paddr = sbase +
        (FPOFF + (wr0 + (ltile & 1) * 8 + lr) * FPSTR + (ltile >> 1) * 4) * 4;

    float m0 = -1e30f, m1 = -1e30f, z0 = 0.f, z1 = 0.f;
    float oacc[8][4];
#pragma unroll
    for (int na = 0; na < 8; na++)
#pragma unroll
        for (int e = 0; e < 4; e++) oacc[na][e] = 0.f;

    for (int it = 0; it < 8; it++) {
        const int buf = it & 1;
        cp_wait<1>(); __syncthreads();

        float sacc[16][4];
#pragma unroll
        for (int na = 0; na < 16; na++)
#pragma unroll
            for (int e = 0; e < 4; e++) sacc[na][e] = 0.f;
        const uint32_t kboff = (uint32_t)buf * FKSTG * 4;
#pragma unroll
        for (int ka = 0; ka < 8; ka++) {
            uint32_t kf[16][2];
#pragma unroll
            for (int p = 0; p < 8; p++)
                ldsm4(kf[2 * p][0], kf[2 * p][1], kf[2 * p + 1][0],
                      kf[2 * p + 1][1], kaddr[p] + kboff + ka * 32);
#pragma unroll
            for (int na = 0; na < 16; na++)
                mma_tf32(sacc[na], qf[ka], kf[na]);
        }

        if (it < 7) {
            float* kd = sm + ((it + 1) & 1) * FKSTG;
#pragma unroll
            for (int i = 0; i < 8; i++) {
                int vi = tid + i * 256; int r = vi >> 4; int c = (vi & 15) << 2;
                cp16(&kd[r * FKSTR + c],
                     kz + (size_t)((it + 1) * 128 + r) * 2048 + c);
            }
            cp_commit();
        }

        float t0 = -1e30f, t1 = -1e30f;
#pragma unroll
        for (int na = 0; na < 16; na++) {
            t0 = fmaxf(t0, fmaxf(sacc[na][0], sacc[na][1]));
            t1 = fmaxf(t1, fmaxf(sacc[na][2], sacc[na][3]));
        }
        t0 = fmaxf(t0, __shfl_xor_sync(0xffffffffu, t0, 1));
        t0 = fmaxf(t0, __shfl_xor_sync(0xffffffffu, t0, 2));
        t1 = fmaxf(t1, __shfl_xor_sync(0xffffffffu, t1, 1));
        t1 = fmaxf(t1, __shfl_xor_sync(0xffffffffu, t1, 2));
        float mn0 = fmaxf(m0, t0), mn1 = fmaxf(m1, t1);
        float sc0 = __expf(m0 - mn0), sc1 = __expf(m1 - mn1);
        m0 = mn0; m1 = mn1;
        z0 *= sc0; z1 *= sc1;
#pragma unroll
        for (int na = 0; na < 8; na++) {
            oacc[na][0] *= sc0; oacc[na][1] *= sc0;
            oacc[na][2] *= sc1; oacc[na][3] *= sc1;
        }
        float s0 = 0.f, s1 = 0.f;
#pragma unroll
        for (int na = 0; na < 16; na++) {
            float p0 = __expf(sacc[na][0] - mn0), p1 = __expf(sacc[na][1] - mn0);
            float p2 = __expf(sacc[na][2] - mn1), p3 = __expf(sacc[na][3] - mn1);
            s0 += p0 + p1; s1 += p2 + p3;
            int c0 = na * 8 + tq * 2;
            *reinterpret_cast<float2*>(&sm[FPOFF + (wr0 + g) * FPSTR + c0]) =
                make_float2(tf32r(p0), tf32r(p1));
            *reinterpret_cast<float2*>(&sm[FPOFF + (wr0 + g + 8) * FPSTR + c0]) =
                make_float2(tf32r(p2), tf32r(p3));
        }
        s0 += __shfl_xor_sync(0xffffffffu, s0, 1);
        s0 += __shfl_xor_sync(0xffffffffu, s0, 2);
        s1 += __shfl_xor_sync(0xffffffffu, s1, 1);
        s1 += __shfl_xor_sync(0xffffffffu, s1, 2);
        z0 += s0; z1 += s1;

        if (it < 7) { cp_wait<1>(); } else { cp_wait<0>(); }
        __syncthreads();

        const uint32_t* vb =
            reinterpret_cast<const uint32_t*>(sm + FVOFF + buf * FKSTG);
#pragma unroll
        for (int ks = 0; ks < 16; ks++) {
            uint32_t pf[4];
            ldsm4(pf[0], pf[1], pf[2], pf[3], paddr + ks * 32);
#pragma unroll
            for (int na = 0; na < 8; na++) {
                uint32_t bb[2];
                bb[0] = vb[(ks * 8 + tq) * FKSTR + na * 8 + g];
                bb[1] = vb[(ks * 8 + tq + 4) * FKSTR + na * 8 + g];
                mma_tf32(oacc[na], pf, bb);
            }
        }
        __syncthreads();
        if (it < 7) {
            float* vd = sm + FVOFF + ((it + 1) & 1) * FKSTG;
#pragma unroll
            for (int i = 0; i < 8; i++) {
                int vi = tid + i * 256; int r = vi >> 4; int c = (vi & 15) << 2;
                cp16(&vd[r * FKSTR + c],
                     vz + (size_t)((it + 1) * 128 + r) * 2048 + c);
            }
            cp_commit();
        }
    }

    const int n = z >> 4, h = z & 15;
    float mf0 = fmaxf(m0, 0.f), mf1 = fmaxf(m1, 0.f);
    float sc0 = __expf(m0 - mf0), sc1 = __expf(m1 - mf1);
    float ep0 = __expf(-mf0), ep1 = __expf(-mf1);
    float zf0 = z0 * sc0 + ep0, zf1 = z1 * sc1 + ep1;
    float inv0 = 1.f / zf0, inv1 = 1.f / zf1;
    float wp0 = tf32r(ep0 * inv0), wp1 = tf32r(ep1 * inv1);
    float f0 = sc0 * inv0, f1 = sc1 * inv1;
    int l0 = lt * 128 + wr0 + g, l1 = l0 + 8;
    if (tq == 0) {
        msav [z * LLQ + l0] = mf0;  msav [z * LLQ + l1] = mf1;
        zisav[z * LLQ + l0] = inv0; zisav[z * LLQ + l1] = inv1;
    }
    const float* nz = noise + z * 64;
    float* a0 = attn + (size_t)(l0 * 2 + n) * 1024 + h * 64;
    float* a1 = attn + (size_t)(l1 * 2 + n) * 1024 + h * 64;
#pragma unroll
    for (int na = 0; na < 8; na++) {
        int d0 = na * 8 + tq * 2;
        float n0 = tf32r(nz[d0]), n1 = tf32r(nz[d0 + 1]);
        float v00 = tf32r(oacc[na][0] * f0 + wp0 * n0);
        float v01 = tf32r(oacc[na][1] * f0 + wp0 * n1);
        float v10 = tf32r(oacc[na][2] * f1 + wp1 * n0);
        float v11 = tf32r(oacc[na][3] * f1 + wp1 * n1);
        *reinterpret_cast<float2*>(a0 + d0) = make_float2(v00, v01);
        *reinterpret_cast<float2*>(a1 + d0) = make_float2(v10, v11);
    }
}

// ================= attn_map recompute (last layer, fast exp) =================
#define SEG_SMEM (4 * FKSTG * 4)   // 139264 B
__global__ void __launch_bounds__(256, 1)
segmap_kernel(const float* __restrict__ q, const float* __restrict__ k,
              const float* __restrict__ msav, const float* __restrict__ zisav,
              float* __restrict__ outm)
{
    extern __shared__ __align__(16) float sm[];
    const int st = blockIdx.x, lt = blockIdx.y, n = blockIdx.z;
    const int tid = threadIdx.x, wid = tid >> 5, lane = tid & 31;
    const int g = lane >> 2, tq = lane & 3;
    const int ltile = lane >> 3, lr = lane & 7;
    const int wr0 = wid * 16;
    const uint32_t sbase = (uint32_t)__cvta_generic_to_shared(sm);

    auto issue = [&](int h) {
        int z = n * 16 + h, buf = h & 1;
        const float* qz = q + z * 64;
        const float* kz = k + z * 64;
        float* qd = sm + buf * FKSTG;
        float* kd = sm + (2 + buf) * FKSTG;
#pragma unroll
        for (int i = 0; i < 8; i++) {
            int vi = tid + i * 256; int r = vi >> 4; int c = (vi & 15) << 2;
            cp16(&qd[r * FKSTR + c], qz + (size_t)(lt * 128 + r) * 2048 + c);
        }
#pragma unroll
        for (int i = 0; i < 8; i++) {
            int vi = tid + i * 256; int r = vi >> 4; int c = (vi & 15) << 2;
            cp16(&kd[r * FKSTR + c], kz + (size_t)(st * 128 + r) * 2048 + c);
        }
        cp_commit();
    };

    float macc[16][4];
#pragma unroll
    for (int na = 0; na < 16; na++)
#pragma unroll
        for (int e = 0; e < 4; e++) macc[na][e] = 0.f;

    issue(0);
    for (int h = 0; h < 16; h++) {
        cp_wait<0>(); __syncthreads();
        if (h < 15) issue(h + 1);
        const int z = n * 16 + h, buf = h & 1;
        const uint32_t qaddr = sbase +
            (buf * FKSTG + (wr0 + (ltile & 1) * 8 + lr) * FKSTR
             + (ltile >> 1) * 4) * 4;
        const uint32_t kbase = sbase + ((2 + buf) * FKSTG) * 4;

        float sacc[16][4];
#pragma unroll
        for (int na = 0; na < 16; na++)
#pragma unroll
            for (int e = 0; e < 4; e++) sacc[na][e] = 0.f;
#pragma unroll
        for (int ka = 0; ka < 8; ka++) {
            uint32_t qf[4];
            ldsm4(qf[0], qf[1], qf[2], qf[3], qaddr + ka * 32);
            uint32_t kf[16][2];
#pragma unroll
            for (int p = 0; p < 8; p++)
                ldsm4(kf[2 * p][0], kf[2 * p][1], kf[2 * p + 1][0],
                      kf[2 * p + 1][1],
                      kbase + ((p * 16 + (ltile >> 1) * 8 + lr) * FKSTR
                               + (ltile & 1) * 4) * 4 + ka * 32);
#pragma unroll
            for (int na = 0; na < 16; na++)
                mma_tf32(sacc[na], qf, kf[na]);
        }
        int l0 = lt * 128 + wr0 + g;
        float mm0 = msav[z * LLQ + l0],     zi0 = zisav[z * LLQ + l0];
        float mm1 = msav[z * LLQ + l0 + 8], zi1 = zisav[z * LLQ + l0 + 8];
#pragma unroll
        for (int na = 0; na < 16; na++) {
            float w0 = __expf(sacc[na][0] - mm0) * zi0;
            float w1 = __expf(sacc[na][1] - mm0) * zi0;
            float w2 = __expf(sacc[na][2] - mm1) * zi1;
            float w3 = __expf(sacc[na][3] - mm1) * zi1;
            macc[na][0] += __fdividef(1.f, 1.f + __expf(-w0));
            macc[na][1] += __fdividef(1.f, 1.f + __expf(-w1));
            macc[na][2] += __fdividef(1.f, 1.f + __expf(-w2));
            macc[na][3] += __fdividef(1.f, 1.f + __expf(-w3));
        }
    }

    size_t base = (size_t)ROWS_T * DDIM + (size_t)n * LLQ * SS;
    int l0 = lt * 128 + wr0 + g;
#pragma unroll
    for (int na = 0; na < 16; na++) {
        int c0 = st * 128 + na * 8 + tq * 2;
        *reinterpret_cast<float2*>(&outm[base + (size_t)l0 * SS + c0]) =
            make_float2(macc[na][0] * (1.f / HH), macc[na][1] * (1.f / HH));
        *reinterpret_cast<float2*>(&outm[base + (size_t)(l0 + 8) * SS + c0]) =
            make_float2(macc[na][2] * (1.f / HH), macc[na][3] * (1.f / HH));
    }
}

// ---------------- layernorm over D=1024; optional tf32-rounded copy ----------------
__global__ void ln_kernel(const float* __restrict__ x, const float* __restrict__ g,
                          const float* __restrict__ b, float* __restrict__ y,
                          float* __restrict__ yr) {
    long long row = blockIdx.x;
    const float4* px = reinterpret_cast<const float4*>(x + row * (long long)DDIM);
    int t = threadIdx.x;
    float4 v = px[t];
    __shared__ float r1[256], r2[256];
    r1[t] = v.x + v.y + v.z + v.w;
    r2[t] = v.x*v.x + v.y*v.y + v.z*v.z + v.w*v.w;
    __syncthreads();
    for (int o = 128; o > 0; o >>= 1) {
        if (t < o) { r1[t] += r1[t + o]; r2[t] += r2[t + o]; }
        __syncthreads();
    }
    float mu  = r1[0] * (1.f / DDIM);
    float var = r2[0] * (1.f / DDIM) - mu * mu;
    float rs  = rsqrtf(var + 1e-5f);
    float4 gg = reinterpret_cast<const float4*>(g)[t];
    float4 bb = reinterpret_cast<const float4*>(b)[t];
    float4 o4;
    o4.x = (v.x - mu) * rs * gg.x + bb.x;
    o4.y = (v.y - mu) * rs * gg.y + bb.y;
    o4.z = (v.z - mu) * rs * gg.z + bb.z;
    o4.w = (v.w - mu) * rs * gg.w + bb.w;
    reinterpret_cast<float4*>(y + row * (long long)DDIM)[t] = o4;
    if (yr) {
        float4 q4;
        q4.x = tf32r(o4.x); q4.y = tf32r(o4.y);
        q4.z = tf32r(o4.z); q4.w = tf32r(o4.w);
        reinterpret_cast<float4*>(yr + row * (long long)DDIM)[t] = q4;
    }
}

// ---------------- host launchers ----------------
static const int SMEM_TB = 3 * (128 * 36 + 128 * 36) * 4;   // 110592 B

static void gemm_tb(int M, int Nn, int K,
                    const float* A, int lda, long long sA,
                    const float* B, int ldb, long long sB,
                    const float* bias, int bstride, float alpha,
                    const float* resid, int ldr, int relu, int roundc,
                    float* C, int ldc, long long sC, int batch) {
    cudaFuncSetAttribute(mma_gemm<128, 128, 64, 32>,
                         cudaFuncAttributeMaxDynamicSharedMemorySize, SMEM_TB);
    dim3 grid(Nn / 128, M / 128, batch), blk(256);
    mma_gemm<128, 128, 64, 32><<<grid, blk, SMEM_TB>>>(
        M, Nn, K, A, lda, sA, B, ldb, sB, bias, bstride, alpha,
        resid, ldr, relu, roundc, C, ldc, sC);
}

extern "C" void kernel_launch(void* const* d_in, const int* in_sizes, int n_in,
                              void* d_out, int out_size) {
    const float* key_in    = (const float*)d_in[0];
    const float* value_in  = (const float*)d_in[1];
    const float* query     = (const float*)d_in[2];
    const float* in_proj_w = (const float*)d_in[3];
    const float* in_proj_b = (const float*)d_in[4];
    const float* out_w     = (const float*)d_in[5];
    const float* out_b     = (const float*)d_in[6];
    const float* ln1_g     = (const float*)d_in[7];
    const float* ln1_b     = (const float*)d_in[8];
    const float* ln2_g     = (const float*)d_in[9];
    const float* ln2_b     = (const float*)d_in[10];
    const float* ff1_w     = (const float*)d_in[11];
    const float* ff1_b     = (const float*)d_in[12];
    const float* ff2_w     = (const float*)d_in[13];
    const float* ff2_b     = (const float*)d_in[14];
    float* out = (float*)d_out;

    float *q, *kv, *attn, *x1, *x, *hbuf, *y, *tgt, *noise, *msav, *zisav;
    float *ipw, *oww, *f1w, *f2w, *kvr, *qryr, *xr, *tgtr;
    cudaGetSymbolAddress((void**)&q,     g_q);
    cudaGetSymbolAddress((void**)&kv,    g_kv);
    cudaGetSymbolAddress((void**)&attn,  g_attn);
    cudaGetSymbolAddress((void**)&x1,    g_x1);
    cudaGetSymbolAddress((void**)&x,     g_x);
    cudaGetSymbolAddress((void**)&hbuf,  g_h);
    cudaGetSymbolAddress((void**)&y,     g_y);
    cudaGetSymbolAddress((void**)&tgt,   g_tgt);
    cudaGetSymbolAddress((void**)&noise, g_noise);
    cudaGetSymbolAddress((void**)&msav,  g_m);
    cudaGetSymbolAddress((void**)&zisav, g_zi);
    cudaGetSymbolAddress((void**)&ipw,   g_ipw);
    cudaGetSymbolAddress((void**)&oww,   g_oww);
    cudaGetSymbolAddress((void**)&f1w,   g_f1w);
    cudaGetSymbolAddress((void**)&f2w,   g_f2w);
    cudaGetSymbolAddress((void**)&kvr,   g_kvr);
    cudaGetSymbolAddress((void**)&qryr,  g_qryr);
    cudaGetSymbolAddress((void**)&xr,    g_xr);
    cudaGetSymbolAddress((void**)&tgtr,  g_tgtr);

    float* kbuf = kv;
    float* vbuf = kv + (size_t)ROWS_S * DDIM;

    cudaFuncSetAttribute(flash_kernel,
                         cudaFuncAttributeMaxDynamicSharedMemorySize, FL_SMEM);
    cudaFuncSetAttribute(segmap_kernel,
                         cudaFuncAttributeMaxDynamicSharedMemorySize, SEG_SMEM);

    // single merged pre-rounding launch
    {
        RC rc;
        const float* srcs[7] = {in_proj_w, out_w, ff1_w, ff2_w,
                                key_in, value_in, query};
        float* dsts[7] = {ipw, oww, f1w, f2w,
                          kvr, kvr + (size_t)ROWS_S * DDIM, qryr};
        long long ns[7] = {(long long)NL*3*DDIM*DDIM, (long long)NL*DDIM*DDIM,
                           (long long)NL*FFD*DDIM, (long long)NL*DDIM*FFD,
                           (long long)ROWS_S*DDIM, (long long)ROWS_S*DDIM,
                           (long long)ROWS_T*DDIM};
        long long tot4 = 0;
        for (int s = 0; s < 7; s++) {
            rc.s[s] = (const float4*)srcs[s];
            rc.d[s] = (float4*)dsts[s];
            rc.n4[s] = (int)(ns[s] / 4);
            tot4 += rc.n4[s];
        }
        round_all<<<(int)((tot4 + 255) / 256), 256>>>(rc);
    }
    noise_kernel<<<(NL * 2048 + 255) / 256, 256>>>(noise);

    for (int i = 0; i < NL; i++) {
        const float* tinr = (i == 0) ? qryr : tgtr;
        const float* tine = (i == 0) ? query : tgt;
        const float* W    = ipw + (size_t)i * 3 * DDIM * DDIM;
        const float* Bb   = in_proj_b + (size_t)i * 3 * DDIM;

        // q projection
        gemm_tb(ROWS_T, DDIM, DDIM, tinr, DDIM, 0, W, DDIM, 0,
                Bb, 0, SCALING, nullptr, 0, 0, 1, q, DDIM, 0, 1);
        // k & v projections batched (z=2)
        gemm_tb(ROWS_S, DDIM, DDIM,
                kvr, DDIM, (long long)ROWS_S * DDIM,
                W + DDIM * DDIM, DDIM, (long long)DDIM * DDIM,
                Bb + DDIM, DDIM, 1.f, nullptr, 0, 0, 1,
                kv, DDIM, (long long)ROWS_S * DDIM, 2);

        // fused attention
        {
            dim3 fg(LLQ / 128, NB * HH);
            flash_kernel<<<fg, 256, FL_SMEM>>>(
                q, kbuf, vbuf, noise + (size_t)i * NB * HH * HDIM,
                attn, msav, zisav);
        }
        if (i == NL - 1) {
            dim3 sg(SS / 128, LLQ / 128, NB);
            segmap_kernel<<<sg, 256, SEG_SMEM>>>(q, kbuf, msav, zisav, out);
        }

        // out-proj + residual -> LN1
        gemm_tb(ROWS_T, DDIM, DDIM, attn, DDIM, 0, oww + (size_t)i * DDIM * DDIM,
                DDIM, 0, out_b + i * DDIM, 0, 1.f, tine, DDIM, 0, 0,
                x1, DDIM, 0, 1);
        ln_kernel<<<ROWS_T, 256>>>(x1, ln1_g + i * DDIM, ln1_b + i * DDIM, x, xr);

        // FFN
        gemm_tb(ROWS_T, FFD, DDIM, xr, DDIM, 0, f1w + (size_t)i * FFD * DDIM,
                DDIM, 0, ff1_b + i * FFD, 0, 1.f, nullptr, 0, 1, 1,
                hbuf, FFD, 0, 1);
        gemm_tb(ROWS_T, DDIM, FFD, hbuf, FFD, 0, f2w + (size_t)i * DDIM * FFD,
                FFD, 0, ff2_b + i * DDIM, 0, 1.f, x, DDIM, 0, 0,
                y, DDIM, 0, 1);

        if (i == NL - 1)
            ln_kernel<<<ROWS_T, 256>>>(y, ln2_g + i * DDIM, ln2_b + i * DDIM,
                                       out, nullptr);
        else
            ln_kernel<<<ROWS_T, 256>>>(y, ln2_g + i * DDIM, ln2_b + i * DDIM,
                                       tgt, tgtr);
    }
}

// round 15
// speedup vs baseline: 1.5574x; 1.5574x over previous
#include <cuda_runtime.h>
#include <cstdint>
#include <math.h>

// ---------------- problem constants ----------------
#define NL   2
#define DDIM 1024
#define HH   16
#define HDIM 64
#define FFD  4096
#define SS   1024
#define NB   2
#define LLQ  4096
#define ROWS_T (LLQ*NB)   // 8192 query rows
#define ROWS_S (SS*NB)    // 2048 kv rows
#define SCALING 0.125f    // HD^-0.5

// ---------------- device scratch (static, allocation-free) ----------------
__device__ float g_q   [ROWS_T*DDIM];
__device__ float g_kv  [2*ROWS_S*DDIM];     // k then v
__device__ float g_attn[ROWS_T*DDIM];
__device__ float g_x1  [ROWS_T*DDIM];
__device__ float g_x   [ROWS_T*DDIM];
__device__ float g_h   [ROWS_T*FFD];
__device__ float g_y   [ROWS_T*DDIM];
__device__ float g_tgt [ROWS_T*DDIM];
__device__ float g_noise[NL*NB*HH*HDIM];
__device__ float g_m   [NB*HH*LLQ];
__device__ float g_zi  [NB*HH*LLQ];
// pre-rounded (tf32) copies
__device__ float g_ipw [NL*3*DDIM*DDIM];
__device__ float g_oww [NL*DDIM*DDIM];
__device__ float g_f1w [NL*FFD*DDIM];
__device__ float g_f2w [NL*DDIM*FFD];
__device__ float g_kvr [2*ROWS_S*DDIM];     // rounded key_in then value_in
__device__ float g_qryr[ROWS_T*DDIM];
__device__ float g_xr  [ROWS_T*DDIM];
__device__ float g_tgtr[ROWS_T*DDIM];

// ---------------- TF32 rounding ----------------
__device__ __forceinline__ float tf32r(float x) {
    asm("cvt.rna.tf32.f32 %0, %0;" : "+f"(x));
    return x;
}

// ---------------- merged pre-rounding (one launch) ----------------
struct RC {
    const float4* s[7];
    float4*       d[7];
    int           n4[7];
};
__global__ void round_all(RC rc) {
    int i = blockIdx.x * blockDim.x + threadIdx.x;
#pragma unroll
    for (int seg = 0; seg < 7; seg++) {
        if (i < rc.n4[seg]) {
            float4 t = rc.s[seg][i];
            t.x = tf32r(t.x); t.y = tf32r(t.y);
            t.z = tf32r(t.z); t.w = tf32r(t.w);
            rc.d[seg][i] = t;
            return;
        }
        i -= rc.n4[seg];
    }
}

// ---------------- cp.async helpers ----------------
__device__ __forceinline__ void cp16(void* s, const void* g) {
    uint32_t sa = (uint32_t)__cvta_generic_to_shared(s);
    asm volatile("cp.async.cg.shared.global [%0], [%1], 16;" :: "r"(sa), "l"(g));
}
__device__ __forceinline__ void cp_commit() {
    asm volatile("cp.async.commit_group;");
}
template<int N>
__device__ __forceinline__ void cp_wait() {
    asm volatile("cp.async.wait_group %0;" :: "n"(N));
}

// ---------------- ldmatrix (tf32 fragments via b16 tiles) ----------------
__device__ __forceinline__ void ldsm4(uint32_t& r0, uint32_t& r1,
                                      uint32_t& r2, uint32_t& r3, uint32_t addr) {
    asm volatile("ldmatrix.sync.aligned.m8n8.x4.shared.b16 {%0,%1,%2,%3}, [%4];"
                 : "=r"(r0), "=r"(r1), "=r"(r2), "=r"(r3) : "r"(addr));
}

// ---------------- JAX threefry2x32 (partitionable) ----------------
__device__ __forceinline__ uint32_t rotl32(uint32_t x, int d) {
    return (x << d) | (x >> (32 - d));
}
__device__ __forceinline__ void threefry2x32(uint32_t k0, uint32_t k1,
                                             uint32_t& x0, uint32_t& x1) {
    uint32_t ks2 = k0 ^ k1 ^ 0x1BD11BDAu;
    x0 += k0; x1 += k1;
#define TFR(r) { x0 += x1; x1 = rotl32(x1, (r)); x1 ^= x0; }
    TFR(13) TFR(15) TFR(26) TFR(6)
    x0 += k1; x1 += ks2 + 1u;
    TFR(17) TFR(29) TFR(16) TFR(24)
    x0 += ks2; x1 += k0 + 2u;
    TFR(13) TFR(15) TFR(26) TFR(6)
    x0 += k0; x1 += k1 + 3u;
    TFR(17) TFR(29) TFR(16) TFR(24)
    x0 += k1; x1 += ks2 + 4u;
    TFR(13) TFR(15) TFR(26) TFR(6)
    x0 += ks2; x1 += k0 + 5u;
#undef TFR
}
__device__ __forceinline__ float bits_to_normal(uint32_t b) {
    float f = __uint_as_float((b >> 9) | 0x3F800000u) - 1.0f;   // [0,1)
    const float lo = -0.99999994f;
    float u = fmaxf(lo, f * 2.0f + lo);
    return 1.4142135623730951f * erfinvf(u);
}
__global__ void noise_kernel(float* __restrict__ noise) {
    int j = blockIdx.x * blockDim.x + threadIdx.x;
    if (j >= NL * 2048) return;
    int layer = j / 2048, jj = j % 2048;
    uint32_t k0 = 0u, k1 = 42u, x0 = 0u, x1 = (uint32_t)layer;
    threefry2x32(k0, k1, x0, x1);
    uint32_t b0 = 0u, b1 = (uint32_t)jj;
    threefry2x32(x0, x1, b0, b1);
    noise[layer * 2048 + jj] = bits_to_normal(b0 ^ b1);
}

// ---------------- TF32 tensor-core GEMM (mma.sync.m16n8k8) ----------------
__device__ __forceinline__ void mma_tf32(float* d, const uint32_t* a, const uint32_t* b) {
    asm volatile(
        "mma.sync.aligned.m16n8k8.row.col.f32.tf32.tf32.f32 "
        "{%0,%1,%2,%3}, {%4,%5,%6,%7}, {%8,%9}, {%0,%1,%2,%3};\n"
        : "+f"(d[0]), "+f"(d[1]), "+f"(d[2]), "+f"(d[3])
        : "r"(a[0]), "r"(a[1]), "r"(a[2]), "r"(a[3]), "r"(b[0]), "r"(b[1]));
}

// ================= generic GEMM: 3-stage cp.async, one sync per k-step ======
template<int BM, int BN, int WM, int WN>
__global__ __launch_bounds__(256, 2)
void mma_gemm(int M, int Nn, int K,
              const float* __restrict__ A, int lda, long long sA,
              const float* __restrict__ B, int ldb, long long sB,
              const float* __restrict__ bias, int bstride, float alpha,
              const float* __restrict__ resid, int ldr, int relu, int roundc,
              float* __restrict__ C, int ldc, long long sC)
{
    constexpr int BK = 32;
    constexpr int STG = 3;
    constexpr int SA  = BK + 4;                   // 36
    constexpr int ASTG = BM * SA;
    constexpr int BSTG = BN * SA;

    extern __shared__ __align__(16) float smem[];
    float* As = smem;
    float* Bs = smem + STG * ASTG;

    long long bz = blockIdx.z;
    A += bz * sA; B += bz * sB; C += bz * sC;
    if (bias) bias += bz * bstride;
    const int bm = blockIdx.y * BM;
    const int bn = blockIdx.x * BN;
    const int tid = threadIdx.x;
    const int wid = tid >> 5, lane = tid & 31;
    const int g = lane >> 2, tq = lane & 3;
    constexpr int WX = BN / WN;
    const int wm = (wid / WX) * WM, wn = (wid % WX) * WN;
    constexpr int MA = WM / 16, NA = WN / 8;

    float acc[MA][NA][4];
#pragma unroll
    for (int i = 0; i < MA; i++)
#pragma unroll
        for (int j = 0; j < NA; j++)
#pragma unroll
            for (int e = 0; e < 4; e++) acc[i][j][e] = 0.f;

    const int ltile = lane >> 3, lr = lane & 7;
    const uint32_t s_base = (uint32_t)__cvta_generic_to_shared(smem);
    uint32_t baseA[MA];
#pragma unroll
    for (int ma = 0; ma < MA; ma++)
        baseA[ma] = ((wm + ma * 16 + (ltile & 1) * 8 + lr) * SA
                     + (ltile >> 1) * 4) * 4;
    uint32_t baseB[(NA + 1) / 2];
#pragma unroll
    for (int p = 0; p < NA / 2; p++)
        baseB[p] = ((wn + p * 16 + (ltile >> 1) * 8 + lr) * SA
                    + (ltile & 1) * 4) * 4;

    auto load_tiles = [&](int st, int k0) {
        float* as = As + st * ASTG;
        float* bs = Bs + st * BSTG;
#pragma unroll
        for (int it = 0; it < BM * BK / (4 * 256); it++) {
            int vi = tid + it * 256;
            int r  = vi >> 3;
            int kc = (vi & 7) * 4;
            cp16(&as[r * SA + kc], A + (long long)(bm + r) * lda + k0 + kc);
        }
#pragma unroll
        for (int it = 0; it < BN * BK / (4 * 256); it++) {
            int vi = tid + it * 256;
            int r  = vi >> 3;
            int kc = (vi & 7) * 4;
            cp16(&bs[r * SA + kc], B + (long long)(bn + r) * ldb + k0 + kc);
        }
    };

    const int nk = K / BK;
    load_tiles(0, 0);      cp_commit();
    load_tiles(1, BK);     cp_commit();

    for (int i = 0; i < nk; i++) {
        if (i == nk - 1) { cp_wait<0>(); } else { cp_wait<1>(); }
        __syncthreads();   // stage i published; stage (i-1) consumers all done
        if (i + 2 < nk) {  // refill buffer (i-1)%3 with stage i+2
            load_tiles((i + 2) % STG, (i + 2) * BK);
            cp_commit();
        }

        const int buf = i % STG;
        const uint32_t s_as = s_base + buf * ASTG * 4;
        const uint32_t s_bs = s_base + (STG * ASTG + buf * BSTG) * 4;

#pragma unroll
        for (int ka = 0; ka < BK / 8; ka++) {
            const int kb = ka * 8;
            uint32_t af[MA][4];
            uint32_t bf[NA][2];
#pragma unroll
            for (int ma = 0; ma < MA; ma++)
                ldsm4(af[ma][0], af[ma][1], af[ma][2], af[ma][3],
                      s_as + baseA[ma] + kb * 4);
#pragma unroll
            for (int p = 0; p < NA / 2; p++)
                ldsm4(bf[2 * p][0], bf[2 * p][1], bf[2 * p + 1][0],
                      bf[2 * p + 1][1], s_bs + baseB[p] + kb * 4);
#pragma unroll
            for (int ma = 0; ma < MA; ma++)
#pragma unroll
                for (int na = 0; na < NA; na++)
                    mma_tf32(acc[ma][na], af[ma], bf[na]);
        }
    }

#pragma unroll
    for (int ma = 0; ma < MA; ma++) {
#pragma unroll
        for (int na = 0; na < NA; na++) {
            int c0 = bn + wn + na * 8 + tq * 2;
#pragma unroll
            for (int hh = 0; hh < 2; hh++) {
                long long rr = bm + wm + ma * 16 + g + hh * 8;
                float v0 = acc[ma][na][hh * 2 + 0];
                float v1 = acc[ma][na][hh * 2 + 1];
                if (bias) { v0 += bias[c0]; v1 += bias[c0 + 1]; }
                v0 *= alpha; v1 *= alpha;
                if (resid) {
                    float2 rv = *reinterpret_cast<const float2*>(
                        resid + rr * (long long)ldr + c0);
                    v0 += rv.x; v1 += rv.y;
                }
                if (relu) { v0 = fmaxf(v0, 0.f); v1 = fmaxf(v1, 0.f); }
                if (roundc) { v0 = tf32r(v0); v1 = tf32r(v1); }
                *reinterpret_cast<float2*>(C + rr * (long long)ldc + c0) =
                    make_float2(v0, v1);
            }
        }
    }
}

// ================= fused flash attention (fast exp) =================
#define FKSTR 68
#define FPSTR 132
#define FKSTG (128*FKSTR)
#define FVOFF (2*FKSTG)
#define FPOFF (4*FKSTG)
#define FL_SMEM ((4*FKSTG + 128*FPSTR) * 4)   // 206848 B

__global__ void __launch_bounds__(256, 1)
flash_kernel(const float* __restrict__ q, const float* __restrict__ k,
             const float* __restrict__ v, const float* __restrict__ noise,
             float* __restrict__ attn, float* __restrict__ msav,
             float* __restrict__ zisav)
{
    extern __shared__ __align__(16) float sm[];
    const int z = blockIdx.y, lt = blockIdx.x;
    const int tid = threadIdx.x, wid = tid >> 5, lane = tid & 31;
    const int g = lane >> 2, tq = lane & 3;
    const int ltile = lane >> 3, lr = lane & 7;
    const int wr0 = wid * 16;
    const float* qz = q + z * 64;
    const float* kz = k + z * 64;
    const float* vz = v + z * 64;
    const uint32_t sbase = (uint32_t)__cvta_generic_to_shared(sm);

#pragma unroll
    for (int i = 0; i < 8; i++) {
        int vi = tid + i * 256; int r = vi >> 4; int c = (vi & 15) << 2;
        cp16(&sm[FPOFF + r * FKSTR + c], qz + (size_t)(lt * 128 + r) * 2048 + c);
    }
    cp_commit();
#pragma unroll
    for (int i = 0; i < 8; i++) {
        int vi = tid + i * 256; int r = vi >> 4; int c = (vi & 15) << 2;
        cp16(&sm[r * FKSTR + c], kz + (size_t)r * 2048 + c);
    }
    cp_commit();
#pragma unroll
    for (int i = 0; i < 8; i++) {
        int vi = tid + i * 256; int r = vi >> 4; int c = (vi & 15) << 2;
        cp16(&sm[FVOFF + r * FKSTR + c], vz + (size_t)r * 2048 + c);
    }
    cp_commit();

    cp_wait<2>(); __syncthreads();
    uint32_t qf[8][4];
    {
        uint32_t qaddr = sbase +
            (FPOFF + (wr0 + (ltile & 1) * 8 + lr) * FKSTR + (ltile >> 1) * 4) * 4;
#pragma unroll
        for (int ka = 0; ka < 8; ka++)
            ldsm4(qf[ka][0], qf[ka][1], qf[ka][2], qf[ka][3], qaddr + ka * 32);
    }
    __syncthreads();

    uint32_t kaddr[8];
#pragma unroll
    for (int p = 0; p < 8; p++)
        kaddr[p] = sbase + ((p * 16 + (ltile >> 1) * 8 + lr) * FKSTR
                            + (ltile & 1) * 4) * 4;
    const uint32_t paddr = sbase +
        (FPOFF + (wr0 + (ltile & 1) * 8 + lr) * FPSTR + (ltile >> 1) * 4) * 4;

    float m0 = -1e30f, m1 = -1e30f, z0 = 0.f, z1 = 0.f;
    float oacc[8][4];
#pragma unroll
    for (int na = 0; na < 8; na++)
#pragma unroll
        for (int e = 0; e < 4; e++) oacc[na][e] = 0.f;

    for (int it = 0; it < 8; it++) {
        const int buf = it & 1;
        cp_wait<1>(); __syncthreads();

        float sacc[16][4];
#pragma unroll
        for (int na = 0; na < 16; na++)
#pragma unroll
            for (int e = 0; e < 4; e++) sacc[na][e] = 0.f;
        const uint32_t kboff = (uint32_t)buf * FKSTG * 4;
#pragma unroll
        for (int ka = 0; ka < 8; ka++) {
            uint32_t kf[16][2];
#pragma unroll
            for (int p = 0; p < 8; p++)
                ldsm4(kf[2 * p][0], kf[2 * p][1], kf[2 * p + 1][0],
                      kf[2 * p + 1][1], kaddr[p] + kboff + ka * 32);
#pragma unroll
            for (int na = 0; na < 16; na++)
                mma_tf32(sacc[na], qf[ka], kf[na]);
        }

        if (it < 7) {
            float* kd = sm + ((it + 1) & 1) * FKSTG;
#pragma unroll
            for (int i = 0; i < 8; i++) {
                int vi = tid + i * 256; int r = vi >> 4; int c = (vi & 15) << 2;
                cp16(&kd[r * FKSTR + c],
                     kz + (size_t)((it + 1) * 128 + r) * 2048 + c);
            }
            cp_commit();
        }

        float t0 = -1e30f, t1 = -1e30f;
#pragma unroll
        for (int na = 0; na < 16; na++) {
            t0 = fmaxf(t0, fmaxf(sacc[na][0], sacc[na][1]));
            t1 = fmaxf(t1, fmaxf(sacc[na][2], sacc[na][3]));
        }
        t0 = fmaxf(t0, __shfl_xor_sync(0xffffffffu, t0, 1));
        t0 = fmaxf(t0, __shfl_xor_sync(0xffffffffu, t0, 2));
        t1 = fmaxf(t1, __shfl_xor_sync(0xffffffffu, t1, 1));
        t1 = fmaxf(t1, __shfl_xor_sync(0xffffffffu, t1, 2));
        float mn0 = fmaxf(m0, t0), mn1 = fmaxf(m1, t1);
        float sc0 = __expf(m0 - mn0), sc1 = __expf(m1 - mn1);
        m0 = mn0; m1 = mn1;
        z0 *= sc0; z1 *= sc1;
#pragma unroll
        for (int na = 0; na < 8; na++) {
            oacc[na][0] *= sc0; oacc[na][1] *= sc0;
            oacc[na][2] *= sc1; oacc[na][3] *= sc1;
        }
        float s0 = 0.f, s1 = 0.f;
#pragma unroll
        for (int na = 0; na < 16; na++) {
            float p0 = __expf(sacc[na][0] - mn0), p1 = __expf(sacc[na][1] - mn0);
            float p2 = __expf(sacc[na][2] - mn1), p3 = __expf(sacc[na][3] - mn1);
            s0 += p0 + p1; s1 += p2 + p3;
            int c0 = na * 8 + tq * 2;
            *reinterpret_cast<float2*>(&sm[FPOFF + (wr0 + g) * FPSTR + c0]) =
                make_float2(tf32r(p0), tf32r(p1));
            *reinterpret_cast<float2*>(&sm[FPOFF + (wr0 + g + 8) * FPSTR + c0]) =
                make_float2(tf32r(p2), tf32r(p3));
        }
        s0 += __shfl_xor_sync(0xffffffffu, s0, 1);
        s0 += __shfl_xor_sync(0xffffffffu, s0, 2);
        s1 += __shfl_xor_sync(0xffffffffu, s1, 1);
        s1 += __shfl_xor_sync(0xffffffffu, s1, 2);
        z0 += s0; z1 += s1;

        if (it < 7) { cp_wait<1>(); } else { cp_wait<0>(); }
        __syncthreads();

        const uint32_t* vb =
            reinterpret_cast<const uint32_t*>(sm + FVOFF + buf * FKSTG);
#pragma unroll
        for (int ks = 0; ks < 16; ks++) {
            uint32_t pf[4];
            ldsm4(pf[0], pf[1], pf[2], pf[3], paddr + ks * 32);
#pragma unroll
            for (int na = 0; na < 8; na++) {
                uint32_t bb[2];
                bb[0] = vb[(ks * 8 + tq) * FKSTR + na * 8 + g];
                bb[1] = vb[(ks * 8 + tq + 4) * FKSTR + na * 8 + g];
                mma_tf32(oacc[na], pf, bb);
            }
        }
        __syncthreads();
        if (it < 7) {
            float* vd = sm + FVOFF + ((it + 1) & 1) * FKSTG;
#pragma unroll
            for (int i = 0; i < 8; i++) {
                int vi = tid + i * 256; int r = vi >> 4; int c = (vi & 15) << 2;
                cp16(&vd[r * FKSTR + c],
                     vz + (size_t)((it + 1) * 128 + r) * 2048 + c);
            }
            cp_commit();
        }
    }

    const int n = z >> 4, h = z & 15;
    float mf0 = fmaxf(m0, 0.f), mf1 = fmaxf(m1, 0.f);
    float sc0 = __expf(m0 - mf0), sc1 = __expf(m1 - mf1);
    float ep0 = __expf(-mf0), ep1 = __expf(-mf1);
    float zf0 = z0 * sc0 + ep0, zf1 = z1 * sc1 + ep1;
    float inv0 = 1.f / zf0, inv1 = 1.f / zf1;
    float wp0 = tf32r(ep0 * inv0), wp1 = tf32r(ep1 * inv1);
    float f0 = sc0 * inv0, f1 = sc1 * inv1;
    int l0 = lt * 128 + wr0 + g, l1 = l0 + 8;
    if (tq == 0) {
        msav [z * LLQ + l0] = mf0;  msav [z * LLQ + l1] = mf1;
        zisav[z * LLQ + l0] = inv0; zisav[z * LLQ + l1] = inv1;
    }
    const float* nz = noise + z * 64;
    float* a0 = attn + (size_t)(l0 * 2 + n) * 1024 + h * 64;
    float* a1 = attn + (size_t)(l1 * 2 + n) * 1024 + h * 64;
#pragma unroll
    for (int na = 0; na < 8; na++) {
        int d0 = na * 8 + tq * 2;
        float n0 = tf32r(nz[d0]), n1 = tf32r(nz[d0 + 1]);
        float v00 = tf32r(oacc[na][0] * f0 + wp0 * n0);
        float v01 = tf32r(oacc[na][1] * f0 + wp0 * n1);
        float v10 = tf32r(oacc[na][2] * f1 + wp1 * n0);
        float v11 = tf32r(oacc[na][3] * f1 + wp1 * n1);
        *reinterpret_cast<float2*>(a0 + d0) = make_float2(v00, v01);
        *reinterpret_cast<float2*>(a1 + d0) = make_float2(v10, v11);
    }
}

// ================= attn_map recompute (last layer, fast exp) =================
#define SEG_SMEM (4 * FKSTG * 4)   // 139264 B
__global__ void __launch_bounds__(256, 1)
segmap_kernel(const float* __restrict__ q, const float* __restrict__ k,
              const float* __restrict__ msav, const float* __restrict__ zisav,
              float* __restrict__ outm)
{
    extern __shared__ __align__(16) float sm[];
    const int st = blockIdx.x, lt = blockIdx.y, n = blockIdx.z;
    const int tid = threadIdx.x, wid = tid >> 5, lane = tid & 31;
    const int g = lane >> 2, tq = lane & 3;
    const int ltile = lane >> 3, lr = lane & 7;
    const int wr0 = wid * 16;
    const uint32_t sbase = (uint32_t)__cvta_generic_to_shared(sm);

    auto issue = [&](int h) {
        int z = n * 16 + h, buf = h & 1;
        const float* qz = q + z * 64;
        const float* kz = k + z * 64;
        float* qd = sm + buf * FKSTG;
        float* kd = sm + (2 + buf) * FKSTG;
#pragma unroll
        for (int i = 0; i < 8; i++) {
            int vi = tid + i * 256; int r = vi >> 4; int c = (vi & 15) << 2;
            cp16(&qd[r * FKSTR + c], qz + (size_t)(lt * 128 + r) * 2048 + c);
        }
#pragma unroll
        for (int i = 0; i < 8; i++) {
            int vi = tid + i * 256; int r = vi >> 4; int c = (vi & 15) << 2;
            cp16(&kd[r * FKSTR + c], kz + (size_t)(st * 128 + r) * 2048 + c);
        }
        cp_commit();
    };

    float macc[16][4];
#pragma unroll
    for (int na = 0; na < 16; na++)
#pragma unroll
        for (int e = 0; e < 4; e++) macc[na][e] = 0.f;

    issue(0);
    for (int h = 0; h < 16; h++) {
        cp_wait<0>(); __syncthreads();
        if (h < 15) issue(h + 1);
        const int z = n * 16 + h, buf = h & 1;
        const uint32_t qaddr = sbase +
            (buf * FKSTG + (wr0 + (ltile & 1) * 8 + lr) * FKSTR
             + (ltile >> 1) * 4) * 4;
        const uint32_t kbase = sbase + ((2 + buf) * FKSTG) * 4;

        float sacc[16][4];
#pragma unroll
        for (int na = 0; na < 16; na++)
#pragma unroll
            for (int e = 0; e < 4; e++) sacc[na][e] = 0.f;
#pragma unroll
        for (int ka = 0; ka < 8; ka++) {
            uint32_t qf[4];
            ldsm4(qf[0], qf[1], qf[2], qf[3], qaddr + ka * 32);
            uint32_t kf[16][2];
#pragma unroll
            for (int p = 0; p < 8; p++)
                ldsm4(kf[2 * p][0], kf[2 * p][1], kf[2 * p + 1][0],
                      kf[2 * p + 1][1],
                      kbase + ((p * 16 + (ltile >> 1) * 8 + lr) * FKSTR
                               + (ltile & 1) * 4) * 4 + ka * 32);
#pragma unroll
            for (int na = 0; na < 16; na++)
                mma_tf32(sacc[na], qf, kf[na]);
        }
        int l0 = lt * 128 + wr0 + g;
        float mm0 = msav[z * LLQ + l0],     zi0 = zisav[z * LLQ + l0];
        float mm1 = msav[z * LLQ + l0 + 8], zi1 = zisav[z * LLQ + l0 + 8];
#pragma unroll
        for (int na = 0; na < 16; na++) {
            float w0 = __expf(sacc[na][0] - mm0) * zi0;
            float w1 = __expf(sacc[na][1] - mm0) * zi0;
            float w2 = __expf(sacc[na][2] - mm1) * zi1;
            float w3 = __expf(sacc[na][3] - mm1) * zi1;
            macc[na][0] += __fdividef(1.f, 1.f + __expf(-w0));
            macc[na][1] += __fdividef(1.f, 1.f + __expf(-w1));
            macc[na][2] += __fdividef(1.f, 1.f + __expf(-w2));
            macc[na][3] += __fdividef(1.f, 1.f + __expf(-w3));
        }
    }

    size_t base = (size_t)ROWS_T * DDIM + (size_t)n * LLQ * SS;
    int l0 = lt * 128 + wr0 + g;
#pragma unroll
    for (int na = 0; na < 16; na++) {
        int c0 = st * 128 + na * 8 + tq * 2;
        *reinterpret_cast<float2*>(&outm[base + (size_t)l0 * SS + c0]) =
            make_float2(macc[na][0] * (1.f / HH), macc[na][1] * (1.f / HH));
        *reinterpret_cast<float2*>(&outm[base + (size_t)(l0 + 8) * SS + c0]) =
            make_float2(macc[na][2] * (1.f / HH), macc[na][3] * (1.f / HH));
    }
}

// ---------------- layernorm over D=1024 (shuffle reduction) ----------------
__global__ void ln_kernel(const float* __restrict__ x, const float* __restrict__ g,
                          const float* __restrict__ b, float* __restrict__ y,
                          float* __restrict__ yr) {
    long long row = blockIdx.x;
    const float4* px = reinterpret_cast<const float4*>(x + row * (long long)DDIM);
    int t = threadIdx.x;
    int wid = t >> 5, lane = t & 31;
    float4 v = px[t];
    float s1 = v.x + v.y + v.z + v.w;
    float s2 = v.x*v.x + v.y*v.y + v.z*v.z + v.w*v.w;
#pragma unroll
    for (int o = 16; o > 0; o >>= 1) {
        s1 += __shfl_xor_sync(0xffffffffu, s1, o);
        s2 += __shfl_xor_sync(0xffffffffu, s2, o);
    }
    __shared__ float w1[8], w2[8];
    if (lane == 0) { w1[wid] = s1; w2[wid] = s2; }
    __syncthreads();
    if (wid == 0) {
        float a1 = (lane < 8) ? w1[lane] : 0.f;
        float a2 = (lane < 8) ? w2[lane] : 0.f;
#pragma unroll
        for (int o = 4; o > 0; o >>= 1) {
            a1 += __shfl_xor_sync(0xffffffffu, a1, o);
            a2 += __shfl_xor_sync(0xffffffffu, a2, o);
        }
        if (lane == 0) { w1[0] = a1; w2[0] = a2; }
    }
    __syncthreads();
    float mu  = w1[0] * (1.f / DDIM);
    float var = w2[0] * (1.f / DDIM) - mu * mu;
    float rs  = rsqrtf(var + 1e-5f);
    float4 gg = reinterpret_cast<const float4*>(g)[t];
    float4 bb = reinterpret_cast<const float4*>(b)[t];
    float4 o4;
    o4.x = (v.x - mu) * rs * gg.x + bb.x;
    o4.y = (v.y - mu) * rs * gg.y + bb.y;
    o4.z = (v.z - mu) * rs * gg.z + bb.z;
    o4.w = (v.w - mu) * rs * gg.w + bb.w;
    reinterpret_cast<float4*>(y + row * (long long)DDIM)[t] = o4;
    if (yr) {
        float4 q4;
        q4.x = tf32r(o4.x); q4.y = tf32r(o4.y);
        q4.z = tf32r(o4.z); q4.w = tf32r(o4.w);
        reinterpret_cast<float4*>(yr + row * (long long)DDIM)[t] = q4;
    }
}

// ---------------- host launchers ----------------
static const int SMEM_TB = 3 * (128 * 36 + 128 * 36) * 4;   // 110592 B

static void gemm_tb(int M, int Nn, int K,
                    const float* A, int lda, long long sA,
                    const float* B, int ldb, long long sB,
                    const float* bias, int bstride, float alpha,
                    const float* resid, int ldr, int relu, int roundc,
                    float* C, int ldc, long long sC, int batch) {
    cudaFuncSetAttribute(mma_gemm<128, 128, 64, 32>,
                         cudaFuncAttributeMaxDynamicSharedMemorySize, SMEM_TB);
    dim3 grid(Nn / 128, M / 128, batch), blk(256);
    mma_gemm<128, 128, 64, 32><<<grid, blk, SMEM_TB>>>(
        M, Nn, K, A, lda, sA, B, ldb, sB, bias, bstride, alpha,
        resid, ldr, relu, roundc, C, ldc, sC);
}

extern "C" void kernel_launch(void* const* d_in, const int* in_sizes, int n_in,
                              void* d_out, int out_size) {
    const float* key_in    = (const float*)d_in[0];
    const float* value_in  = (const float*)d_in[1];
    const float* query     = (const float*)d_in[2];
    const float* in_proj_w = (const float*)d_in[3];
    const float* in_proj_b = (const float*)d_in[4];
    const float* out_w     = (const float*)d_in[5];
    const float* out_b     = (const float*)d_in[6];
    const float* ln1_g     = (const float*)d_in[7];
    const float* ln1_b     = (const float*)d_in[8];
    const float* ln2_g     = (const float*)d_in[9];
    const float* ln2_b     = (const float*)d_in[10];
    const float* ff1_w     = (const float*)d_in[11];
    const float* ff1_b     = (const float*)d_in[12];
    const float* ff2_w     = (const float*)d_in[13];
    const float* ff2_b     = (const float*)d_in[14];
    float* out = (float*)d_out;

    float *q, *kv, *attn, *x1, *x, *hbuf, *y, *tgt, *noise, *msav, *zisav;
    float *ipw, *oww, *f1w, *f2w, *kvr, *qryr, *xr, *tgtr;
    cudaGetSymbolAddress((void**)&q,     g_q);
    cudaGetSymbolAddress((void**)&kv,    g_kv);
    cudaGetSymbolAddress((void**)&attn,  g_attn);
    cudaGetSymbolAddress((void**)&x1,    g_x1);
    cudaGetSymbolAddress((void**)&x,     g_x);
    cudaGetSymbolAddress((void**)&hbuf,  g_h);
    cudaGetSymbolAddress((void**)&y,     g_y);
    cudaGetSymbolAddress((void**)&tgt,   g_tgt);
    cudaGetSymbolAddress((void**)&noise, g_noise);
    cudaGetSymbolAddress((void**)&msav,  g_m);
    cudaGetSymbolAddress((void**)&zisav, g_zi);
    cudaGetSymbolAddress((void**)&ipw,   g_ipw);
    cudaGetSymbolAddress((void**)&oww,   g_oww);
    cudaGetSymbolAddress((void**)&f1w,   g_f1w);
    cudaGetSymbolAddress((void**)&f2w,   g_f2w);
    cudaGetSymbolAddress((void**)&kvr,   g_kvr);
    cudaGetSymbolAddress((void**)&qryr,  g_qryr);
    cudaGetSymbolAddress((void**)&xr,    g_xr);
    cudaGetSymbolAddress((void**)&tgtr,  g_tgtr);

    float* kbuf = kv;
    float* vbuf = kv + (size_t)ROWS_S * DDIM;

    cudaFuncSetAttribute(flash_kernel,
                         cudaFuncAttributeMaxDynamicSharedMemorySize, FL_SMEM);
    cudaFuncSetAttribute(segmap_kernel,
                         cudaFuncAttributeMaxDynamicSharedMemorySize, SEG_SMEM);

    // single merged pre-rounding launch
    {
        RC rc;
        const float* srcs[7] = {in_proj_w, out_w, ff1_w, ff2_w,
                                key_in, value_in, query};
        float* dsts[7] = {ipw, oww, f1w, f2w,
                          kvr, kvr + (size_t)ROWS_S * DDIM, qryr};
        long long ns[7] = {(long long)NL*3*DDIM*DDIM, (long long)NL*DDIM*DDIM,
                           (long long)NL*FFD*DDIM, (long long)NL*DDIM*FFD,
                           (long long)ROWS_S*DDIM, (long long)ROWS_S*DDIM,
                           (long long)ROWS_T*DDIM};
        long long tot4 = 0;
        for (int s = 0; s < 7; s++) {
            rc.s[s] = (const float4*)srcs[s];
            rc.d[s] = (float4*)dsts[s];
            rc.n4[s] = (int)(ns[s] / 4);
            tot4 += rc.n4[s];
        }
        round_all<<<(int)((tot4 + 255) / 256), 256>>>(rc);
    }
    noise_kernel<<<(NL * 2048 + 255) / 256, 256>>>(noise);

    for (int i = 0; i < NL; i++) {
        const float* tinr = (i == 0) ? qryr : tgtr;
        const float* tine = (i == 0) ? query : tgt;
        const float* W    = ipw + (size_t)i * 3 * DDIM * DDIM;
        const float* Bb   = in_proj_b + (size_t)i * 3 * DDIM;

        // q projection
        gemm_tb(ROWS_T, DDIM, DDIM, tinr, DDIM, 0, W, DDIM, 0,
                Bb, 0, SCALING, nullptr, 0, 0, 1, q, DDIM, 0, 1);
        // k & v projections batched (z=2)
        gemm_tb(ROWS_S, DDIM, DDIM,
                kvr, DDIM, (long long)ROWS_S * DDIM,
                W + DDIM * DDIM, DDIM, (long long)DDIM * DDIM,
                Bb + DDIM, DDIM, 1.f, nullptr, 0, 0, 1,
                kv, DDIM, (long long)ROWS_S * DDIM, 2);

        // fused attention
        {
            dim3 fg(LLQ / 128, NB * HH);
            flash_kernel<<<fg, 256, FL_SMEM>>>(
                q, kbuf, vbuf, noise + (size_t)i * NB * HH * HDIM,
                attn, msav, zisav);
        }
        if (i == NL - 1) {
            dim3 sg(SS / 128, LLQ / 128, NB);
            segmap_kernel<<<sg, 256, SEG_SMEM>>>(q, kbuf, msav, zisav, out);
        }

        // out-proj + residual -> LN1
        gemm_tb(ROWS_T, DDIM, DDIM, attn, DDIM, 0, oww + (size_t)i * DDIM * DDIM,
                DDIM, 0, out_b + i * DDIM, 0, 1.f, tine, DDIM, 0, 0,
                x1, DDIM, 0, 1);
        ln_kernel<<<ROWS_T, 256>>>(x1, ln1_g + i * DDIM, ln1_b + i * DDIM, x, xr);

        // FFN
        gemm_tb(ROWS_T, FFD, DDIM, xr, DDIM, 0, f1w + (size_t)i * FFD * DDIM,
                DDIM, 0, ff1_b + i * FFD, 0, 1.f, nullptr, 0, 1, 1,
                hbuf, FFD, 0, 1);
        gemm_tb(ROWS_T, DDIM, FFD, hbuf, FFD, 0, f2w + (size_t)i * DDIM * FFD,
                FFD, 0, ff2_b + i * DDIM, 0, 1.f, x, DDIM, 0, 0,
                y, DDIM, 0, 1);

        if (i == NL - 1)
            ln_kernel<<<ROWS_T, 256>>>(y, ln2_g + i * DDIM, ln2_b + i * DDIM,
                                       out, nullptr);
        else
            ln_kernel<<<ROWS_T, 256>>>(y, ln2_g + i * DDIM, ln2_b + i * DDIM,
                                       tgt, tgtr);
    }
}